// round 9
// baseline (speedup 1.0000x reference)
#include <cuda_runtime.h>
#include <cuda_bf16.h>
#include <cstdint>
#include <math.h>

#define NT      2048
#define DMODEL  2048
#define NHEAD   16
#define DHEAD   128
#define INNERD  2048
#define FFI     8192
#define VOCAB   32000
#define NLAYER  4
#define EPSF    1e-5f
#define MASKV   1e-10f
#define KT      32
#define ASTR    40     // [row][k] smem stride (elems) for A and trans-B tiles
#define BSTRN   136    // [k][n] smem stride (elems) for NN B tiles
#define L2E     1.4426950408889634f
#define PERS_GRID 304  // 152 SMs * 2 CTAs

typedef __nv_bfloat16 bf16;

// ---------------- scratch (static device globals; no allocations) ----------------
__device__ float g_x [NT * DMODEL];
__device__ bf16  g_hh[NT * DMODEL], g_hl[NT * DMODEL];
__device__ bf16  g_qh[NT * INNERD], g_ql[NT * INNERD];
__device__ float g_kv [NT * 256];                          // fused [k | v] fp32
__device__ bf16  g_kvh[NT * 256], g_kvl[NT * 256];         // fused [k | v] pairs
__device__ float g_suf[NT * DHEAD];                        // suffixV
__device__ float g_c  [NHEAD * NT];                        // per-row masked prob
__device__ float g_S [(size_t)NHEAD * NT * NT];
__device__ bf16  g_Ph[(size_t)NHEAD * NT * NT], g_Pl[(size_t)NHEAD * NT * NT];
__device__ bf16  g_aoh[NT * INNERD], g_aol[NT * INNERD];
__device__ float g_f1[NT * FFI], g_f2[NT * FFI];           // g_f1 reused as PV fp32 out
__device__ bf16  g_f1h[NT * FFI], g_f1l[NT * FFI];
// pre-split weights (layouts as given by reference)
__device__ bf16 w_qh [NLAYER * DMODEL * INNERD], w_ql [NLAYER * DMODEL * INNERD];
__device__ bf16 w_kvh[NLAYER * DMODEL * 256],    w_kvl[NLAYER * DMODEL * 256];   // interleaved wk|wv
__device__ bf16 w_oh [NLAYER * INNERD * DMODEL], w_ol [NLAYER * INNERD * DMODEL];
__device__ bf16 w_ih [(size_t)NLAYER * DMODEL * FFI], w_il [(size_t)NLAYER * DMODEL * FFI];
__device__ bf16 w_gh [(size_t)NLAYER * DMODEL * FFI], w_gl [(size_t)NLAYER * DMODEL * FFI];
__device__ bf16 w_foh[(size_t)NLAYER * FFI * DMODEL], w_fol[(size_t)NLAYER * FFI * DMODEL];
__device__ bf16 w_eh [(size_t)VOCAB * DMODEL], w_el [(size_t)VOCAB * DMODEL];

// ---------------- helpers ----------------
__device__ __forceinline__ void cpa16(uint32_t dst, const void* src) {
    asm volatile("cp.async.cg.shared.global [%0],[%1],16;" :: "r"(dst), "l"(src));
}
__device__ __forceinline__ void ldsm4(uint32_t* r, uint32_t a) {
    asm volatile("ldmatrix.sync.aligned.m8n8.x4.shared.b16 {%0,%1,%2,%3},[%4];"
                 : "=r"(r[0]), "=r"(r[1]), "=r"(r[2]), "=r"(r[3]) : "r"(a));
}
__device__ __forceinline__ void ldsm4t(uint32_t* r, uint32_t a) {
    asm volatile("ldmatrix.sync.aligned.m8n8.x4.trans.shared.b16 {%0,%1,%2,%3},[%4];"
                 : "=r"(r[0]), "=r"(r[1]), "=r"(r[2]), "=r"(r[3]) : "r"(a));
}
__device__ __forceinline__ void mma16816(float* c, const uint32_t* a, uint32_t b0, uint32_t b1) {
    asm volatile("mma.sync.aligned.m16n8k16.row.col.f32.bf16.bf16.f32 "
                 "{%0,%1,%2,%3},{%4,%5,%6,%7},{%8,%9},{%0,%1,%2,%3};"
                 : "+f"(c[0]), "+f"(c[1]), "+f"(c[2]), "+f"(c[3])
                 : "r"(a[0]), "r"(a[1]), "r"(a[2]), "r"(a[3]), "r"(b0), "r"(b1));
}
__device__ __forceinline__ void split1(float a, bf16& h, bf16& l) {
    h = __float2bfloat16_rn(a);
    l = __float2bfloat16_rn(a - __bfloat162float(h));
}
__device__ __forceinline__ void split2_store(bf16* hp, bf16* lp, float a, float b) {
    float ha = __bfloat162float(__float2bfloat16_rn(a));
    float hb = __bfloat162float(__float2bfloat16_rn(b));
    __nv_bfloat162 H = __floats2bfloat162_rn(a, b);
    __nv_bfloat162 L = __floats2bfloat162_rn(a - ha, b - hb);
    *(uint32_t*)hp = *(uint32_t*)&H;
    *(uint32_t*)lp = *(uint32_t*)&L;
}

// ---------------- fp32 -> bf16 pair (straight, vectorized) ----------------
__global__ void __launch_bounds__(256) cvt_pair_kernel(const float* __restrict__ in,
                                                       bf16* __restrict__ ho, bf16* __restrict__ lo) {
    size_t i = (size_t)blockIdx.x * 256 + threadIdx.x;
    float4 v = ((const float4*)in)[i];
    bf16 h0, l0, h1, l1, h2, l2, h3, l3;
    split1(v.x, h0, l0); split1(v.y, h1, l1); split1(v.z, h2, l2); split1(v.w, h3, l3);
    __nv_bfloat162 ha = {h0, h1}, hb = {h2, h3}, la = {l0, l1}, lb = {l2, l3};
    uint2 H = {*(uint32_t*)&ha, *(uint32_t*)&hb};
    uint2 L = {*(uint32_t*)&la, *(uint32_t*)&lb};
    ((uint2*)ho)[i] = H;
    ((uint2*)lo)[i] = L;
}

// ---- strided pair cvt: in [R,128] -> out [R,256] at column offset ----
__global__ void __launch_bounds__(256) cvt_pair_cols_kernel(const float* __restrict__ in,
                                                            bf16* __restrict__ ho, bf16* __restrict__ lo,
                                                            int colOff) {
    size_t i = (size_t)blockIdx.x * 256 + threadIdx.x;   // float4 index over [R,128]
    int row = (int)(i >> 5);
    int col = ((int)i & 31) * 4;
    float4 v = ((const float4*)in)[i];
    size_t o = (size_t)row * 256 + colOff + col;
    bf16 h0, l0, h1, l1, h2, l2, h3, l3;
    split1(v.x, h0, l0); split1(v.y, h1, l1); split1(v.z, h2, l2); split1(v.w, h3, l3);
    __nv_bfloat162 ha = {h0, h1}, hb = {h2, h3}, la = {l0, l1}, lb = {l2, l3};
    *(uint32_t*)(ho + o)     = *(uint32_t*)&ha;
    *(uint32_t*)(ho + o + 2) = *(uint32_t*)&hb;
    *(uint32_t*)(lo + o)     = *(uint32_t*)&la;
    *(uint32_t*)(lo + o + 2) = *(uint32_t*)&lb;
}

// ---------------- embedding ----------------
__global__ void embed_kernel(const int* __restrict__ tok, const float* __restrict__ emb,
                             float* __restrict__ x) {
    int n = blockIdx.x;
    const float* src = emb + (size_t)tok[n] * DMODEL;
    float* dst = x + (size_t)n * DMODEL;
    for (int d = threadIdx.x; d < DMODEL; d += blockDim.x) dst[d] = src[d];
}

// ---------------- RMSNorm -> bf16 pair ----------------
__global__ void __launch_bounds__(256) rmsnorm_pair_kernel(const float* __restrict__ x,
                                                           const float* __restrict__ gamma,
                                                           bf16* __restrict__ oh, bf16* __restrict__ ol) {
    int n = blockIdx.x;
    const float* row = x + (size_t)n * DMODEL;
    float s = 0.f;
    for (int d = threadIdx.x; d < DMODEL; d += 256) { float v = row[d]; s += v * v; }
    __shared__ float red[256];
    red[threadIdx.x] = s; __syncthreads();
    #pragma unroll
    for (int k = 128; k > 0; k >>= 1) {
        if (threadIdx.x < k) red[threadIdx.x] += red[threadIdx.x + k];
        __syncthreads();
    }
    float inv = rsqrtf(red[0] * (1.0f / DMODEL) + EPSF);
    for (int d = threadIdx.x; d < DMODEL; d += 256) {
        bf16 h, l; split1(row[d] * inv * gamma[d], h, l);
        oh[(size_t)n * DMODEL + d] = h;
        ol[(size_t)n * DMODEL + d] = l;
    }
}

// ---------------- SwiGLU -> bf16 pair ----------------
__global__ void __launch_bounds__(256) silu_pair_kernel(const float* __restrict__ a,
                                                        const float* __restrict__ b,
                                                        bf16* __restrict__ oh, bf16* __restrict__ ol) {
    size_t i = (size_t)blockIdx.x * 256 + threadIdx.x;
    float bb = b[i];
    bf16 h, l; split1(a[i] * bb / (1.f + __expf(-bb)), h, l);
    oh[i] = h; ol[i] = l;
}

// ---------------- suffixV: suf[i][d] = sum_{j>i} v[j][d]; v strided in g_kv ----------------
__global__ void __launch_bounds__(128) suffixv_kernel(const float* __restrict__ kv,
                                                      float* __restrict__ suf) {
    const int d = threadIdx.x;
    const int lo = blockIdx.x * 128, hi = lo + 128;
    float acc = 0.f;
    for (int j = NT - 1; j >= hi; --j)
        acc += kv[(size_t)j * 256 + 128 + d];
    for (int i = hi - 1; i >= lo; --i) {
        suf[(size_t)i * DHEAD + d] = acc;
        acc += kv[(size_t)i * 256 + 128 + d];
    }
}

// ------- softmax: visible region exact, masked region rank-1 (c stored) -------
__global__ void __launch_bounds__(256) softmax_kernel(const float* __restrict__ S,
                                                      bf16* __restrict__ Ph, bf16* __restrict__ Pl,
                                                      float* __restrict__ C) {
    const int i = blockIdx.x, h = blockIdx.y, tid = threadIdx.x;
    const float* row = S + ((size_t)h * NT + i) * NT;
    __shared__ float sc[NT];
    __shared__ float red[256];
    const float slope = exp2f(-0.5f * (float)(h + 1));
    const float scale = 0.08838834764831845f;
    const int tileEnd = ((i >> 7) + 1) << 7;    // columns the PV GEMM will read

    float mx = MASKV;                            // masked entries participate in max
    for (int j = tid; j <= i; j += 256) {
        float v = row[j] * scale + slope * (float)j;
        sc[j] = v;
        mx = fmaxf(mx, v);
    }
    red[tid] = mx; __syncthreads();
    #pragma unroll
    for (int s = 128; s > 0; s >>= 1) {
        if (tid < s) red[tid] = fmaxf(red[tid], red[tid + s]);
        __syncthreads();
    }
    mx = red[0]; __syncthreads();

    float sum = 0.f;
    for (int j = tid; j <= i; j += 256) {
        float p = exp2f((sc[j] - mx) * L2E);
        sc[j] = p; sum += p;
    }
    red[tid] = sum; __syncthreads();
    #pragma unroll
    for (int s = 128; s > 0; s >>= 1) {
        if (tid < s) red[tid] += red[tid + s];
        __syncthreads();
    }
    const float maskexp = exp2f((MASKV - mx) * L2E);
    const float inv = 1.f / (red[0] + (float)(NT - 1 - i) * maskexp);
    const float c = maskexp * inv;
    if (tid == 0) C[(size_t)h * NT + i] = c;

    bf16* ph = Ph + ((size_t)h * NT + i) * NT;
    bf16* pl = Pl + ((size_t)h * NT + i) * NT;
    for (int j = tid; j < tileEnd; j += 256) {
        if (j <= i) {
            bf16 hh, ll; split1(sc[j] * inv, hh, ll);
            ph[j] = hh; pl[j] = ll;
        } else {
            ph[j] = __float2bfloat16_rn(0.f);
            pl[j] = __float2bfloat16_rn(0.f);
        }
    }
}

// ------- attention output correction + split: ao = pv + c*suffixV -> bf16 pair -------
__global__ void __launch_bounds__(256) ao_fix_kernel(const float* __restrict__ pv,
                                                     const float* __restrict__ C,
                                                     const float* __restrict__ suf,
                                                     bf16* __restrict__ oh, bf16* __restrict__ ol) {
    size_t idx = (size_t)blockIdx.x * 256 + threadIdx.x;   // over NT*INNERD
    int i = (int)(idx >> 11);
    int rem = (int)(idx & 2047);
    int h = rem >> 7, d = rem & 127;
    float v = pv[idx] + C[(size_t)h * NT + i] * suf[(size_t)i * DHEAD + d];
    bf16 hh, ll; split1(v, hh, ll);
    oh[idx] = hh; ol[idx] = ll;
}

// ================= pipelined bf16-split tensor-core GEMM =================
// EPI: 0 store fp32, 1 fp32 +=, 2 atomicAdd (split-K), 3 bf16 pair store.
// CAUSAL: 0 none; 1 skip tiles with colBase>rowBase; 2 cap K at rowBase+128.
// PERS: persistent-CTA tile loop (no batching/splitK/causal); prefetches the
//       next tile's first stage before the epilogue to hide drain/fill.
template <int TRANSB, int EPI, int CAUSAL, int PERS>
__global__ void __launch_bounds__(256, 2)
gemm_bf3(const bf16* __restrict__ Ah, const bf16* __restrict__ Al,
         const bf16* __restrict__ Bh, const bf16* __restrict__ Bl,
         float* __restrict__ C, bf16* __restrict__ Ch, bf16* __restrict__ Cl,
         int M, int N, int K, int lda, int ldb, int ldc,
         int kSplit, size_t aZ, size_t bZ, size_t cZ, int nTiles, int nx) {
    extern __shared__ __align__(16) char smem[];
    const int tid = threadIdx.x, lane = tid & 31, warp = tid >> 5;
    const int wm = warp >> 2, wn = warp & 3;
    int rowBase = 0, colBase = 0;
    if (!PERS) {
        rowBase = blockIdx.y * 128; colBase = blockIdx.x * 128;
        if (CAUSAL == 1 && colBase > rowBase) return;
        const int z = blockIdx.z;
        if (kSplit <= 1) {
            Ah += z * aZ; Al += z * aZ; Bh += z * bZ; Bl += z * bZ;
            if (EPI == 3) { Ch += z * cZ; Cl += z * cZ; } else { C += z * cZ; }
        }
    }
    const uint32_t sb = (uint32_t)__cvta_generic_to_shared(smem);
    const int BUFB = TRANSB ? 10240 : 8704;
    const int l15 = lane & 15, lhi = (lane >> 4) * 8;

    auto load_stage = [&](int s, int kt, int rB, int cB) {
        uint32_t aOff = sb + s * 20480;
        uint32_t bOff = sb + 40960 + s * 2 * BUFB;
        #pragma unroll
        for (int r = 0; r < 2; ++r) {
            int idx = tid + r * 256;
            int row = idx >> 2, kc = (idx & 3) * 8;
            uint32_t d = aOff + (row * ASTR + kc) * 2;
            const size_t ga = (size_t)(rB + row) * lda + kt + kc;
            cpa16(d,         Ah + ga);
            cpa16(d + 10240, Al + ga);
            if (!TRANSB) {
                int kr = idx >> 4, nc = (idx & 15) * 8;
                uint32_t db = bOff + (kr * BSTRN + nc) * 2;
                const size_t gb = (size_t)(kt + kr) * ldb + cB + nc;
                cpa16(db,        Bh + gb);
                cpa16(db + BUFB, Bl + gb);
            } else {
                int nr = idx >> 2, kc2 = (idx & 3) * 8;
                uint32_t db = bOff + (nr * ASTR + kc2) * 2;
                const size_t gb = (size_t)(cB + nr) * ldb + kt + kc2;
                cpa16(db,        Bh + gb);
                cpa16(db + BUFB, Bl + gb);
            }
        }
        asm volatile("cp.async.commit_group;");
    };

    float acc[4][4][4];
    const int tEnd  = PERS ? nTiles : 1;
    const int tStep = PERS ? gridDim.x : 1;
    bool pre = false;

    for (int t = PERS ? (int)blockIdx.x : 0; t < tEnd; t += tStep) {
        if (PERS) { colBase = (t % nx) * 128; rowBase = (t / nx) * 128; }
        int kStart = 0, kEnd = K;
        if (!PERS) {
            if (CAUSAL == 2) kEnd = rowBase + 128 < K ? rowBase + 128 : K;
            if (kSplit > 1) { int kl = K / kSplit; kStart = blockIdx.z * kl; kEnd = kStart + kl; }
        }
        const int nk = (kEnd - kStart) / KT;

        #pragma unroll
        for (int i = 0; i < 4; ++i)
            #pragma unroll
            for (int j = 0; j < 4; ++j)
                #pragma unroll
                for (int v = 0; v < 4; ++v) acc[i][j][v] = 0.f;

        if (!pre) load_stage(0, kStart, rowBase, colBase);

        for (int it = 0; it < nk; ++it) {
            const int s = it & 1;
            if (it + 1 < nk) {
                load_stage((it + 1) & 1, kStart + (it + 1) * KT, rowBase, colBase);
                asm volatile("cp.async.wait_group 1;");
            } else {
                asm volatile("cp.async.wait_group 0;");
            }
            __syncthreads();

            const uint32_t aBase = sb + s * 20480 + ((wm * 64 + l15) * ASTR + lhi) * 2;
            const uint32_t bOff  = sb + 40960 + s * 2 * BUFB;

            #pragma unroll
            for (int ks = 0; ks < KT; ks += 16) {
                uint32_t aH[4][4], aL[4][4], bH[2][4], bL[2][4];
                #pragma unroll
                for (int mt = 0; mt < 4; ++mt)
                    ldsm4(aH[mt], aBase + ks * 2 + mt * (16 * ASTR * 2));
                if (!TRANSB) {
                    uint32_t bBase = bOff + ((l15 + ks) * BSTRN + wn * 32 + lhi) * 2;
                    #pragma unroll
                    for (int p = 0; p < 2; ++p) ldsm4t(bH[p], bBase + p * 32);
                } else {
                    #pragma unroll
                    for (int p = 0; p < 2; ++p)
                        ldsm4(bH[p], bOff + ((wn * 32 + p * 16 + l15) * ASTR + ks + lhi) * 2);
                }
                #pragma unroll
                for (int mt = 0; mt < 4; ++mt)
                    #pragma unroll
                    for (int nt = 0; nt < 4; ++nt) {
                        int p = nt >> 1, su = nt & 1;
                        uint32_t b0 = TRANSB ? bH[p][su]     : bH[p][2 * su];
                        uint32_t b1 = TRANSB ? bH[p][su + 2] : bH[p][2 * su + 1];
                        mma16816(acc[mt][nt], aH[mt], b0, b1);
                    }
                if (!TRANSB) {
                    uint32_t bBase = bOff + BUFB + ((l15 + ks) * BSTRN + wn * 32 + lhi) * 2;
                    #pragma unroll
                    for (int p = 0; p < 2; ++p) ldsm4t(bL[p], bBase + p * 32);
                } else {
                    #pragma unroll
                    for (int p = 0; p < 2; ++p)
                        ldsm4(bL[p], bOff + BUFB + ((wn * 32 + p * 16 + l15) * ASTR + ks + lhi) * 2);
                }
                #pragma unroll
                for (int mt = 0; mt < 4; ++mt)
                    #pragma unroll
                    for (int nt = 0; nt < 4; ++nt) {
                        int p = nt >> 1, su = nt & 1;
                        uint32_t b0 = TRANSB ? bL[p][su]     : bL[p][2 * su];
                        uint32_t b1 = TRANSB ? bL[p][su + 2] : bL[p][2 * su + 1];
                        mma16816(acc[mt][nt], aH[mt], b0, b1);
                    }
                #pragma unroll
                for (int mt = 0; mt < 4; ++mt)
                    ldsm4(aL[mt], aBase + 10240 + ks * 2 + mt * (16 * ASTR * 2));
                #pragma unroll
                for (int mt = 0; mt < 4; ++mt)
                    #pragma unroll
                    for (int nt = 0; nt < 4; ++nt) {
                        int p = nt >> 1, su = nt & 1;
                        uint32_t b0 = TRANSB ? bH[p][su]     : bH[p][2 * su];
                        uint32_t b1 = TRANSB ? bH[p][su + 2] : bH[p][2 * su + 1];
                        mma16816(acc[mt][nt], aL[mt], b0, b1);
                    }
            }
            __syncthreads();
        }

        // ---- prefetch next tile's first stage (overlaps with epilogue) ----
        if (PERS) {
            int tn = t + tStep;
            if (tn < tEnd) {
                load_stage(0, 0, (tn / nx) * 128, (tn % nx) * 128);
                pre = true;
            }
        }

        // ---------- epilogue ----------
        const int r0 = rowBase + wm * 64 + (lane >> 2);
        const int c0 = colBase + wn * 32 + (lane & 3) * 2;
        #pragma unroll
        for (int mt = 0; mt < 4; ++mt) {
            #pragma unroll
            for (int nt = 0; nt < 4; ++nt) {
                int r = r0 + mt * 16, c = c0 + nt * 8;
                if (EPI == 3) {
                    split2_store(Ch + (size_t)r * ldc + c,       Cl + (size_t)r * ldc + c,
                                 acc[mt][nt][0], acc[mt][nt][1]);
                    split2_store(Ch + (size_t)(r + 8) * ldc + c, Cl + (size_t)(r + 8) * ldc + c,
                                 acc[mt][nt][2], acc[mt][nt][3]);
                } else if (EPI == 2) {
                    atomicAdd(C + (size_t)r * ldc + c,           acc[mt][nt][0]);
                    atomicAdd(C + (size_t)r * ldc + c + 1,       acc[mt][nt][1]);
                    atomicAdd(C + (size_t)(r + 8) * ldc + c,     acc[mt][nt][2]);
                    atomicAdd(C + (size_t)(r + 8) * ldc + c + 1, acc[mt][nt][3]);
                } else {
                    float2* p0 = (float2*)(C + (size_t)r * ldc + c);
                    float2* p1 = (float2*)(C + (size_t)(r + 8) * ldc + c);
                    if (EPI == 1) {
                        float2 t0 = *p0, t1 = *p1;
                        t0.x += acc[mt][nt][0]; t0.y += acc[mt][nt][1];
                        t1.x += acc[mt][nt][2]; t1.y += acc[mt][nt][3];
                        *p0 = t0; *p1 = t1;
                    } else {
                        *p0 = make_float2(acc[mt][nt][0], acc[mt][nt][1]);
                        *p1 = make_float2(acc[mt][nt][2], acc[mt][nt][3]);
                    }
                }
            }
        }
    }
}

// ---------------- host-side dispatch ----------------
template <int TRANSB, int EPI, int CAUSAL>
static void launch_gemm(const bf16* Ah, const bf16* Al, const bf16* Bh, const bf16* Bl,
                        float* C, bf16* Ch, bf16* Cl,
                        int M, int N, int K, int lda, int ldb, int ldc,
                        int Z, int kSplit, size_t aZ, size_t bZ, size_t cZ) {
    const int smem = 40960 + 4 * (TRANSB ? 10240 : 8704);
    cudaFuncSetAttribute(gemm_bf3<TRANSB, EPI, CAUSAL, 0>, cudaFuncAttributeMaxDynamicSharedMemorySize, smem);
    dim3 grid(N / 128, M / 128, Z);
    gemm_bf3<TRANSB, EPI, CAUSAL, 0><<<grid, 256, smem>>>(Ah, Al, Bh, Bl, C, Ch, Cl,
                                                          M, N, K, lda, ldb, ldc, kSplit, aZ, bZ, cZ, 0, 1);
}

template <int TRANSB, int EPI>
static void launch_gemm_pers(const bf16* Ah, const bf16* Al, const bf16* Bh, const bf16* Bl,
                             float* C, bf16* Ch, bf16* Cl,
                             int M, int N, int K, int lda, int ldb, int ldc) {
    const int smem = 40960 + 4 * (TRANSB ? 10240 : 8704);
    cudaFuncSetAttribute(gemm_bf3<TRANSB, EPI, 0, 1>, cudaFuncAttributeMaxDynamicSharedMemorySize, smem);
    const int nx = N / 128, nTiles = nx * (M / 128);
    const int grid = nTiles < PERS_GRID ? nTiles : PERS_GRID;
    gemm_bf3<TRANSB, EPI, 0, 1><<<grid, 256, smem>>>(Ah, Al, Bh, Bl, C, Ch, Cl,
                                                     M, N, K, lda, ldb, ldc, 1, 0, 0, 0, nTiles, nx);
}

extern "C" void kernel_launch(void* const* d_in, const int* in_sizes, int n_in,
                              void* d_out, int out_size) {
    const int*   tokens      = (const int*)  d_in[0];
    const float* emb         = (const float*)d_in[1];
    const float* attn_gamma  = (const float*)d_in[2];
    const float* wq          = (const float*)d_in[3];
    const float* wk          = (const float*)d_in[4];
    const float* wv          = (const float*)d_in[5];
    const float* wo          = (const float*)d_in[6];
    const float* ff_gamma    = (const float*)d_in[7];
    const float* wi          = (const float*)d_in[8];
    const float* wg          = (const float*)d_in[9];
    const float* wfo         = (const float*)d_in[10];
    const float* final_gamma = (const float*)d_in[11];
    float* out = (float*)d_out;

    float *x, *kv, *suf, *c, *S, *f1, *f2;
    bf16 *hh, *hl, *qh, *ql, *kvh, *kvl, *Ph, *Pl, *aoh, *aol, *f1h, *f1l;
    bf16 *Wqh, *Wql, *Wkvh, *Wkvl, *Woh, *Wol, *Wih, *Wil, *Wgh, *Wgl, *Wfoh, *Wfol, *Weh, *Wel;
    cudaGetSymbolAddress((void**)&x,    g_x);
    cudaGetSymbolAddress((void**)&hh,   g_hh);  cudaGetSymbolAddress((void**)&hl,  g_hl);
    cudaGetSymbolAddress((void**)&qh,   g_qh);  cudaGetSymbolAddress((void**)&ql,  g_ql);
    cudaGetSymbolAddress((void**)&kv,   g_kv);
    cudaGetSymbolAddress((void**)&kvh,  g_kvh); cudaGetSymbolAddress((void**)&kvl, g_kvl);
    cudaGetSymbolAddress((void**)&suf,  g_suf); cudaGetSymbolAddress((void**)&c,   g_c);
    cudaGetSymbolAddress((void**)&S,    g_S);
    cudaGetSymbolAddress((void**)&Ph,   g_Ph);  cudaGetSymbolAddress((void**)&Pl,  g_Pl);
    cudaGetSymbolAddress((void**)&aoh,  g_aoh); cudaGetSymbolAddress((void**)&aol, g_aol);
    cudaGetSymbolAddress((void**)&f1,   g_f1);  cudaGetSymbolAddress((void**)&f2,  g_f2);
    cudaGetSymbolAddress((void**)&f1h,  g_f1h); cudaGetSymbolAddress((void**)&f1l, g_f1l);
    cudaGetSymbolAddress((void**)&Wqh,  w_qh);  cudaGetSymbolAddress((void**)&Wql, w_ql);
    cudaGetSymbolAddress((void**)&Wkvh, w_kvh); cudaGetSymbolAddress((void**)&Wkvl, w_kvl);
    cudaGetSymbolAddress((void**)&Woh,  w_oh);  cudaGetSymbolAddress((void**)&Wol, w_ol);
    cudaGetSymbolAddress((void**)&Wih,  w_ih);  cudaGetSymbolAddress((void**)&Wil, w_il);
    cudaGetSymbolAddress((void**)&Wgh,  w_gh);  cudaGetSymbolAddress((void**)&Wgl, w_gl);
    cudaGetSymbolAddress((void**)&Wfoh, w_foh); cudaGetSymbolAddress((void**)&Wfol, w_fol);
    cudaGetSymbolAddress((void**)&Weh,  w_eh);  cudaGetSymbolAddress((void**)&Wel, w_el);

    auto cvt = [](const float* in, bf16* h, bf16* l, size_t n) {
        cvt_pair_kernel<<<(unsigned)(n / 1024), 256>>>(in, h, l);
    };

    // ---- weight pre-split (captured; runs each replay) ----
    cvt(wq,  Wqh,  Wql,  (size_t)NLAYER * DMODEL * INNERD);
    cvt(wo,  Woh,  Wol,  (size_t)NLAYER * INNERD * DMODEL);
    cvt(wi,  Wih,  Wil,  (size_t)NLAYER * DMODEL * FFI);
    cvt(wg,  Wgh,  Wgl,  (size_t)NLAYER * DMODEL * FFI);
    cvt(wfo, Wfoh, Wfol, (size_t)NLAYER * FFI * DMODEL);
    cvt(emb, Weh,  Wel,  (size_t)VOCAB * DMODEL);
    for (int l = 0; l < NLAYER; ++l) {
        const size_t okv = (size_t)l * DMODEL * DHEAD;
        const size_t okvW = (size_t)l * DMODEL * 256;
        cvt_pair_cols_kernel<<<(DMODEL * DHEAD) / 1024, 256>>>(wk + okv, Wkvh + okvW, Wkvl + okvW, 0);
        cvt_pair_cols_kernel<<<(DMODEL * DHEAD) / 1024, 256>>>(wv + okv, Wkvh + okvW, Wkvl + okvW, 128);
    }

    embed_kernel<<<NT, 256>>>(tokens, emb, x);

    for (int l = 0; l < NLAYER; ++l) {
        const size_t oq   = (size_t)l * DMODEL * INNERD;
        const size_t okvW = (size_t)l * DMODEL * 256;
        const size_t oi   = (size_t)l * DMODEL * FFI;
        const size_t ofo  = (size_t)l * FFI * DMODEL;

        // --- attention ---
        rmsnorm_pair_kernel<<<NT, 256>>>(x, attn_gamma + (size_t)l * DMODEL, hh, hl);
        launch_gemm_pers<0, 3>(hh, hl, Wqh + oq, Wql + oq, nullptr, qh, ql,
                               NT, INNERD, DMODEL, DMODEL, INNERD, INNERD);
        cudaMemsetAsync(kv, 0, NT * 256 * sizeof(float));
        launch_gemm<0, 2, 0>(hh, hl, Wkvh + okvW, Wkvl + okvW, kv, nullptr, nullptr,
                             NT, 256, DMODEL, DMODEL, 256, 256, 8, 8, 0, 0, 0);
        cvt(kv, kvh, kvl, (size_t)NT * 256);
        suffixv_kernel<<<NT / 128, 128>>>(kv, suf);
        // S[h] = Q_h @ K^T  (skip strictly-upper tiles)
        launch_gemm<1, 0, 1>(qh, ql, kvh, kvl, S, nullptr, nullptr,
                             NT, NT, DHEAD, INNERD, 256, NT,
                             NHEAD, 1, (size_t)DHEAD, 0, (size_t)NT * NT);
        softmax_kernel<<<dim3(NT, NHEAD), 256>>>(S, Ph, Pl, c);
        // pv = P_h @ V  (K capped at diagonal; fp32 into f1 scratch)
        launch_gemm<0, 0, 2>(Ph, Pl, kvh + 128, kvl + 128, f1, nullptr, nullptr,
                             NT, DHEAD, NT, NT, 256, INNERD,
                             NHEAD, 1, (size_t)NT * NT, 0, (size_t)DHEAD);
        ao_fix_kernel<<<(NT * INNERD) / 256, 256>>>(f1, c, suf, aoh, aol);
        launch_gemm_pers<0, 1>(aoh, aol, Woh + oq, Wol + oq, x, nullptr, nullptr,
                               NT, DMODEL, INNERD, INNERD, DMODEL, DMODEL);

        // --- SwiGLU FFN ---
        rmsnorm_pair_kernel<<<NT, 256>>>(x, ff_gamma + (size_t)l * DMODEL, hh, hl);
        launch_gemm_pers<0, 0>(hh, hl, Wih + oi, Wil + oi, f1, nullptr, nullptr,
                               NT, FFI, DMODEL, DMODEL, FFI, FFI);
        launch_gemm_pers<0, 0>(hh, hl, Wgh + oi, Wgl + oi, f2, nullptr, nullptr,
                               NT, FFI, DMODEL, DMODEL, FFI, FFI);
        silu_pair_kernel<<<(NT * FFI) / 256, 256>>>(f1, f2, f1h, f1l);
        launch_gemm_pers<0, 1>(f1h, f1l, Wfoh + ofo, Wfol + ofo, x, nullptr, nullptr,
                               NT, DMODEL, FFI, FFI, DMODEL, DMODEL);
    }

    // --- final norm + tied-embedding logits ---
    rmsnorm_pair_kernel<<<NT, 256>>>(x, final_gamma, hh, hl);
    launch_gemm_pers<1, 0>(hh, hl, Weh, Wel, out, nullptr, nullptr,
                           NT, VOCAB, DMODEL, DMODEL, DMODEL, VOCAB);
}